// round 14
// baseline (speedup 1.0000x reference)
#include <cuda_runtime.h>
#include <math.h>

#define P_   128
#define T_   2048
#define D_   128
#define H_   64
#define G_   192   // 3*H
#define OUT_ 24

typedef unsigned long long u64;

// Scratch (device global: allocation-free per harness rules)
static __device__ float g_hs[(size_t)P_ * T_ * H_];  // [P][T][64]

// ---- packed f32x2 + activation helpers ------------------------------------
__device__ __forceinline__ u64 fma2(u64 a, u64 b, u64 c) {
    u64 d; asm("fma.rn.f32x2 %0, %1, %2, %3;" : "=l"(d) : "l"(a), "l"(b), "l"(c));
    return d;
}
__device__ __forceinline__ u64 add2(u64 a, u64 b) {
    u64 d; asm("add.rn.f32x2 %0, %1, %2;" : "=l"(d) : "l"(a), "l"(b));
    return d;
}
__device__ __forceinline__ u64 pack2(float lo, float hi) {
    u64 r; asm("mov.b64 %0, {%1, %2};" : "=l"(r) : "f"(lo), "f"(hi));
    return r;
}
__device__ __forceinline__ float sum2(u64 v) {
    float lo, hi; asm("mov.b64 {%0, %1}, %2;" : "=f"(lo), "=f"(hi) : "l"(v));
    return lo + hi;
}
__device__ __forceinline__ float tanhapx(float x) {
    float y; asm("tanh.approx.f32 %0, %1;" : "=f"(y) : "f"(x)); return y;
}

// named barriers (memory-clobbered)
#define NB_SYNC(id, cnt)   asm volatile("bar.sync %0, %1;"   :: "r"(id), "r"(cnt) : "memory")
#define NB_ARRIVE(id, cnt) asm volatile("bar.arrive %0, %1;" :: "r"(id), "r"(cnt) : "memory")

// ===========================================================================
// Kernel A: fused x_proj + GRU. 1 CTA/part, 320 threads.
//   threads 0-127  : consumers. thread = (j = tid>>1, half = tid&1); each
//                    computes k-half dots of ALL 3 gates for its j, combines
//                    via shfl.bfly(1), activates in-register. One barrier/step
//                    (double-buffered h).
//   threads 128-319: producers (x-projection). z streamed via TRIPLE-buffered
//                    cp.async ring: at tile k read zbuf[k%3], refill
//                    zbuf[(k+2)%3] (= stage consumed at tile k-1, which all
//                    producers finished before the top-of-tile-k barrier).
//                    This removes the WAR race that round 13 exposed.
// ===========================================================================
#define ZTILE  32
#define NTILES (T_ / ZTILE)   // 64
#define NTHR   320

#define SM_ZBUF   0                       // 3 * 32*128 = 12288
#define SM_XP     (SM_ZBUF + 12288)       // 2 * 32*192 = 12288
#define SM_H      (SM_XP + 12288)         // 2 * 64 (double-buffered h)
#define SM_GRU_TOTAL (SM_H + 128)         // 24704 floats = 98816 B

__global__ __launch_bounds__(NTHR, 1)
void gru_kernel(const float* __restrict__ z,
                const float* __restrict__ w_ih,
                const float* __restrict__ b_ih,
                const float* __restrict__ w_hh,
                const float* __restrict__ b_hh)
{
    extern __shared__ __align__(16) float sm[];
    const int tid = threadIdx.x;
    const int p   = blockIdx.x;
    float* hout = g_hs + (size_t)p * T_ * H_;

    if (tid < 128) {
        // ---------------- consumer ----------------
        const int j    = tid >> 1;
        const int half = tid & 1;

        // 3 gates x 32 weights (k-half) = 48 u64
        u64 whh[3][16];
        #pragma unroll
        for (int g = 0; g < 3; g++) {
            const ulonglong2* wp = (const ulonglong2*)
                (w_hh + ((size_t)p*G_ + g*64 + j) * H_ + 32*half);
            #pragma unroll
            for (int q = 0; q < 8; q++) {
                ulonglong2 v = wp[q];
                whh[g][2*q] = v.x; whh[g][2*q+1] = v.y;
            }
        }
        float bhh[3];
        #pragma unroll
        for (int g = 0; g < 3; g++) bhh[g] = b_hh[p*G_ + g*64 + j];

        float* hb = sm + SM_H;             // [2][64]
        if (half == 0) { hb[j] = 0.f; hb[64 + j] = 0.f; }
        float hreg = 0.f;                  // h_old carried in register
        NB_SYNC(1, 128);

        for (int tile = 0; tile < NTILES; tile++) {
            const int st = tile & 1;
            NB_SYNC(3 + st, NTHR);                      // xp tile full
            const float* xt = sm + SM_XP + st * (ZTILE * 192);

            for (int s = 0; s < ZTILE; s++) {
                const float xpR = xt[s*192 + j];
                const float xpZ = xt[s*192 + 64 + j];
                const float xpN = xt[s*192 + 128 + j];

                const ulonglong2* hr = (const ulonglong2*)
                    (hb + (s & 1)*64 + 32*half);

                u64 aR0 = 0ull, aR1 = 0ull, aZ0 = 0ull, aZ1 = 0ull, aN0 = 0ull, aN1 = 0ull;
                #pragma unroll
                for (int q = 0; q < 8; q++) {
                    ulonglong2 hv2 = hr[q];
                    aR0 = fma2(whh[0][2*q],   hv2.x, aR0);
                    aR1 = fma2(whh[0][2*q+1], hv2.y, aR1);
                    aZ0 = fma2(whh[1][2*q],   hv2.x, aZ0);
                    aZ1 = fma2(whh[1][2*q+1], hv2.y, aZ1);
                    aN0 = fma2(whh[2][2*q],   hv2.x, aN0);
                    aN1 = fma2(whh[2][2*q+1], hv2.y, aN1);
                }
                float pR = sum2(add2(aR0, aR1));
                float pZ = sum2(add2(aZ0, aZ1));
                float pN = sum2(add2(aN0, aN1));
                const float hpR = pR + __shfl_xor_sync(0xffffffffu, pR, 1) + bhh[0];
                const float hpZ = pZ + __shfl_xor_sync(0xffffffffu, pZ, 1) + bhh[1];
                const float hpN = pN + __shfl_xor_sync(0xffffffffu, pN, 1) + bhh[2];

                const float r = 0.5f + 0.5f * tanhapx(0.5f * (xpR + hpR));
                const float u = 0.5f + 0.5f * tanhapx(0.5f * (xpZ + hpZ));
                const float n = tanhapx(xpN + r * hpN);
                const float hv = n + u * (hreg - n);
                hreg = hv;

                if (half == 0) hb[((s + 1) & 1)*64 + j] = hv;   // publish to smem
                else           hout[(size_t)(tile*ZTILE + s) * H_ + j] = hv;
                NB_SYNC(1, 128);                        // one barrier per step
            }
            NB_ARRIVE(5 + st, NTHR);                    // release xp tile
        }
    } else {
        // ---------------- producer ----------------
        const int j = tid - 128;                        // 0..191
        u64 wih[64];
        {
            const ulonglong2* wp = (const ulonglong2*)(w_ih + ((size_t)p*G_ + j) * D_);
            #pragma unroll
            for (int q = 0; q < 32; q++) { ulonglong2 v = wp[q]; wih[2*q] = v.x; wih[2*q+1] = v.y; }
        }
        const float bih = b_ih[p*G_ + j];
        const float* zp = z + (size_t)p * T_ * D_;

        #pragma unroll 1
        for (int tl = 0; tl < 2; tl++) {                // prologue: z tiles 0,1 -> stages 0,1
            const float* src = zp + (size_t)tl * ZTILE * D_;
            for (int i = j; i < ZTILE * D_ / 4; i += 192) {
                unsigned dst = (unsigned)__cvta_generic_to_shared(sm + SM_ZBUF + tl*(ZTILE*D_) + i*4);
                asm volatile("cp.async.cg.shared.global [%0], [%1], 16;" :: "r"(dst), "l"(src + i*4));
            }
            asm volatile("cp.async.commit_group;");
        }

        for (int tile = 0; tile < NTILES; tile++) {
            const int st = tile & 1;
            if (tile < NTILES - 1) asm volatile("cp.async.wait_group 1;");
            else                   asm volatile("cp.async.wait_group 0;");
            NB_SYNC(2, 192);              // all producers: z tile complete + tile-1 reads done
            if (tile >= 2) NB_SYNC(5 + st, NTHR);       // wait xp tile empty

            float*       xt = sm + SM_XP   + st * (ZTILE * 192);
            const float* zt = sm + SM_ZBUF + (tile % 3) * (ZTILE * D_);

            for (int s = 0; s < ZTILE; s++) {
                u64 x0 = 0ull, x1 = 0ull, x2 = 0ull, x3 = 0ull;
                const ulonglong2* zr = (const ulonglong2*)(zt + s * D_);
                #pragma unroll
                for (int q = 0; q < 16; q++) {
                    ulonglong2 a0v = zr[2*q], a1v = zr[2*q+1];
                    x0 = fma2(wih[4*q+0], a0v.x, x0);
                    x1 = fma2(wih[4*q+1], a0v.y, x1);
                    x2 = fma2(wih[4*q+2], a1v.x, x2);
                    x3 = fma2(wih[4*q+3], a1v.y, x3);
                }
                xt[s*192 + j] = (sum2(x0) + sum2(x1)) + (sum2(x2) + sum2(x3)) + bih;
            }
            NB_ARRIVE(3 + st, NTHR);                    // publish xp tile

            if (tile + 2 < NTILES) {
                // refill stage (tile+2)%3 — consumed at tile-1, provably idle
                const float* src = zp + (size_t)(tile + 2) * ZTILE * D_;
                for (int i = j; i < ZTILE * D_ / 4; i += 192) {
                    unsigned dst = (unsigned)__cvta_generic_to_shared(
                        sm + SM_ZBUF + ((tile + 2) % 3)*(ZTILE*D_) + i*4);
                    asm volatile("cp.async.cg.shared.global [%0], [%1], 16;" :: "r"(dst), "l"(src + i*4));
                }
                asm volatile("cp.async.commit_group;");
            }
        }
    }
}

// ===========================================================================
// Kernel B: persistent MLP. 1 CTA/part, 512 threads = 4 groups x 128.
// (unchanged: 315 us, weights loaded once per part)
// ===========================================================================
#define ASTRIDE 132
#define SM_W1   0                         // 128*65 = 8320
#define SM_W2   (SM_W1 + 128*65)          // 64*129 = 8256
#define SM_W3   (SM_W2 + 64*129)          // 32*65  = 2080
#define SM_W4   (SM_W3 + 32*65)           // 24*33  = 792
#define SM_B1   (SM_W4 + 24*33)
#define SM_B2   (SM_B1 + 128)
#define SM_B3   (SM_B2 + 64)
#define SM_B4   (SM_B3 + 32)
#define SM_ACT  (SM_B4 + 24)              // 19696
#define ACT_PER_GRP (2 * 32 * ASTRIDE)    // 8448
#define SM_MLP_TOTAL (SM_ACT + 4*ACT_PER_GRP)   // 53488 floats = 213952 B

template<int I, int O, bool RELU>
__device__ __forceinline__
void mlp_layer128(int lt, const float* __restrict__ ain, float* __restrict__ aout,
                  const float* __restrict__ W, const float* __restrict__ bias)
{
    constexpr int OGN  = O / 4;           // 32 / 16 / 8
    constexpr int TGN  = 128 / OGN;       // 4 / 8 / 16
    constexpr int ROWS = 32 / TGN;        // 8 / 4 / 2
    constexpr int WS   = I + 1;

    const int og = lt % OGN;
    const int tg = lt / OGN;

    u64 acc[ROWS][4];
    #pragma unroll
    for (int r = 0; r < ROWS; r++)
        #pragma unroll
        for (int c = 0; c < 4; c++) acc[r][c] = 0ull;

    const float* arow = ain + tg*ROWS*ASTRIDE;

    #pragma unroll 8
    for (int k = 0; k < I; k += 2) {
        u64 av[ROWS];
        #pragma unroll
        for (int r = 0; r < ROWS; r++)
            av[r] = *(const u64*)(arow + r*ASTRIDE + k);
        #pragma unroll
        for (int c = 0; c < 4; c++) {
            const float* wrow = W + (og + c*OGN)*WS + k;
            u64 bv = pack2(wrow[0], wrow[1]);
            #pragma unroll
            for (int r = 0; r < ROWS; r++)
                acc[r][c] = fma2(av[r], bv, acc[r][c]);
        }
    }

    #pragma unroll
    for (int r = 0; r < ROWS; r++)
        #pragma unroll
        for (int c = 0; c < 4; c++) {
            int o = og + c*OGN;
            float v = sum2(acc[r][c]) + bias[o];
            if (RELU) v = fmaxf(v, 0.f);
            aout[(tg*ROWS + r)*ASTRIDE + o] = v;
        }
}

__global__ __launch_bounds__(512, 1)
void mlp_kernel(const float* __restrict__ w1, const float* __restrict__ b1,
                const float* __restrict__ w2, const float* __restrict__ b2,
                const float* __restrict__ w3, const float* __restrict__ b3,
                const float* __restrict__ w4, const float* __restrict__ b4,
                float* __restrict__ out)
{
    extern __shared__ __align__(16) float sm[];
    const int tid = threadIdx.x;
    const int p   = blockIdx.x;

    float* W1 = sm + SM_W1;  float* W2 = sm + SM_W2;
    float* W3 = sm + SM_W3;  float* W4 = sm + SM_W4;
    float* B1 = sm + SM_B1;  float* B2 = sm + SM_B2;
    float* B3 = sm + SM_B3;  float* B4 = sm + SM_B4;

    {
        const float* wp = w1 + (size_t)p*128*64;
        for (int i = tid; i < 128*64; i += 512) { int o = i >> 6, k = i & 63;  W1[o*65  + k] = wp[i]; }
        wp = w2 + (size_t)p*64*128;
        for (int i = tid; i < 64*128; i += 512) { int o = i >> 7, k = i & 127; W2[o*129 + k] = wp[i]; }
        wp = w3 + (size_t)p*32*64;
        for (int i = tid; i < 32*64;  i += 512) { int o = i >> 6, k = i & 63;  W3[o*65  + k] = wp[i]; }
        wp = w4 + (size_t)p*24*32;
        for (int i = tid; i < 24*32;  i += 512) { int o = i >> 5, k = i & 31;  W4[o*33  + k] = wp[i]; }
    }
    if (tid < 128)                 B1[tid]       = b1[p*128 + tid];
    if (tid >= 128 && tid < 192)   B2[tid - 128] = b2[p*64 + tid - 128];
    if (tid >= 192 && tid < 224)   B3[tid - 192] = b3[p*32 + tid - 192];
    if (tid >= 224 && tid < 248)   B4[tid - 224] = b4[p*24 + tid - 224];
    __syncthreads();

    const int g  = tid >> 7;        // group 0..3
    const int lt = tid & 127;
    float* AA = sm + SM_ACT + g * ACT_PER_GRP;
    float* AB = AA + 32 * ASTRIDE;

    for (int tile = g; tile < T_ / 32; tile += 4) {
        {   // 32x64 hidden rows -> AA (float4, coalesced)
            const float4* hp4 = (const float4*)(g_hs + ((size_t)p*T_ + tile*32) * H_);
            for (int i = lt; i < 32*16; i += 128) {
                int t = i >> 4, kq = i & 15;
                *(float4*)(AA + t*ASTRIDE + kq*4) = hp4[i];
            }
        }
        NB_SYNC(1 + g, 128);        // also orders prev tile's L4 reads of AB

        mlp_layer128<64, 128, true>(lt, AA, AB, W1, B1);
        NB_SYNC(1 + g, 128);
        mlp_layer128<128, 64, true>(lt, AB, AA, W2, B2);
        NB_SYNC(1 + g, 128);
        mlp_layer128<64, 32, true>(lt, AA, AB, W3, B3);
        NB_SYNC(1 + g, 128);

        float* op = out + ((size_t)p*T_ + tile*32) * OUT_;
        for (int i = lt; i < 32*OUT_; i += 128) {
            int t = i / OUT_;
            int o = i - t*OUT_;
            u64 acc = 0ull;
            const float* arow = AB + t*ASTRIDE;
            const float* wrow = W4 + o*33;
            #pragma unroll
            for (int k = 0; k < 32; k += 2)
                acc = fma2(*(const u64*)(arow + k), pack2(wrow[k], wrow[k+1]), acc);
            op[i] = sum2(acc) + B4[o];
        }
    }
}

// ---------------------------------------------------------------------------
extern "C" void kernel_launch(void* const* d_in, const int* in_sizes, int n_in,
                              void* d_out, int out_size)
{
    const float* z    = (const float*)d_in[0];
    const float* w_ih = (const float*)d_in[1];
    const float* w_hh = (const float*)d_in[2];
    const float* b_ih = (const float*)d_in[3];
    const float* b_hh = (const float*)d_in[4];
    const float* w1   = (const float*)d_in[5];
    const float* b1   = (const float*)d_in[6];
    const float* w2   = (const float*)d_in[7];
    const float* b2   = (const float*)d_in[8];
    const float* w3   = (const float*)d_in[9];
    const float* b3   = (const float*)d_in[10];
    const float* w4   = (const float*)d_in[11];
    const float* b4   = (const float*)d_in[12];
    float* out = (float*)d_out;

    const int gru_smem = SM_GRU_TOTAL * 4;   // 98816 B
    const int mlp_smem = SM_MLP_TOTAL * 4;   // 213952 B
    cudaFuncSetAttribute(gru_kernel, cudaFuncAttributeMaxDynamicSharedMemorySize, gru_smem);
    cudaFuncSetAttribute(mlp_kernel, cudaFuncAttributeMaxDynamicSharedMemorySize, mlp_smem);

    gru_kernel<<<P_, NTHR, gru_smem>>>(z, w_ih, b_ih, w_hh, b_hh);
    mlp_kernel<<<P_, 512, mlp_smem>>>(w1, b1, w2, b2, w3, b3, w4, b4, out);
}